// round 8
// baseline (speedup 1.0000x reference)
#include <cuda_runtime.h>
#include <math.h>

// ---------------- scratch (no allocation allowed) ----------------
#define MAXN   262144
#define SCAN_BLK 1024          // threads per scan block
#define TILE   4096            // segments per scan tile (4 per thread)
#define MAX_NB 64
#define FLAG_AGG  0x10000000
#define FLAG_INCL 0x20000000
#define VMASK     0x0FFFFFFF
#define FULL      0xffffffffu
__device__ __align__(16) int2 g_meta[MAXN];  // (exclusive offset, count) per segment
__device__ int    g_state[MAX_NB];   // decoupled-lookback state (zero-init, reset by k_main)
__device__ double g_acc[4];          // lp, la, lw, ls sums
__device__ int    g_done = 0;        // completion counter for folded finalize

// ------ kernel 1: single-pass scan, warp-parallel lookback (<=64 blocks) ------
__global__ void __launch_bounds__(SCAN_BLK) k_scan(const int* __restrict__ counts, int N) {
    __shared__ int wsum[32];
    __shared__ int s_ex;
    int tid = threadIdx.x, lane = tid & 31, w = tid >> 5;
    int base4 = blockIdx.x * TILE + tid * 4;

    int4 v = make_int4(0, 0, 0, 0);
    if (base4 + 3 < N) v = *(const int4*)(counts + base4);
    else {
        if (base4 + 0 < N) v.x = counts[base4 + 0];
        if (base4 + 1 < N) v.y = counts[base4 + 1];
        if (base4 + 2 < N) v.z = counts[base4 + 2];
        if (base4 + 3 < N) v.w = counts[base4 + 3];
    }
    int s = v.x + v.y + v.z + v.w;

    // warp inclusive scan of per-thread sums
    int si = s;
    #pragma unroll
    for (int o = 1; o < 32; o <<= 1) {
        int t = __shfl_up_sync(FULL, si, o);
        if (lane >= o) si += t;
    }
    if (lane == 31) wsum[w] = si;
    __syncthreads();
    if (w == 0) {
        int ws = wsum[lane];
        int wi = ws;
        #pragma unroll
        for (int o = 1; o < 32; o <<= 1) {
            int t = __shfl_up_sync(FULL, wi, o);
            if (lane >= o) wi += t;
        }
        wsum[lane] = wi - ws;                        // exclusive warp offset
        int total = __shfl_sync(FULL, wi, 31);       // tile aggregate

        if (lane == 0) {                             // publish
            if (blockIdx.x == 0) atomicExch(&g_state[0], total | FLAG_INCL);
            else                 atomicExch(&g_state[blockIdx.x], total | FLAG_AGG);
        }
        int ex = 0;
        if (blockIdx.x > 0) {                        // warp-parallel lookback
            int p = (int)blockIdx.x - 1;
            while (true) {
                int idx = p - lane;
                int st = (idx >= 0) ? atomicAdd(&g_state[idx], 0) : FLAG_INCL;
                while (__any_sync(FULL, st == 0))
                    st = (idx >= 0) ? atomicAdd(&g_state[idx], 0) : FLAG_INCL;
                unsigned im = __ballot_sync(FULL, (st & FLAG_INCL) != 0);
                if (im) {
                    int k = __ffs(im) - 1;           // nearest inclusive predecessor
                    int contrib = (lane <= k) ? (st & VMASK) : 0;
                    ex += __reduce_add_sync(FULL, contrib);
                    break;
                } else {
                    ex += __reduce_add_sync(FULL, st & VMASK);
                    p -= 32;
                }
            }
            if (lane == 0) atomicExch(&g_state[blockIdx.x], (ex + total) | FLAG_INCL);
        } else if (lane == 0) {
            g_acc[0] = 0.0; g_acc[1] = 0.0; g_acc[2] = 0.0; g_acc[3] = 0.0;
        }
        if (lane == 0) s_ex = ex;
    }
    __syncthreads();

    int base = s_ex + wsum[w] + (si - s);            // global exclusive prefix
    if (base4 + 3 < N) {
        int4 m0 = make_int4(base,             v.x, base + v.x,        v.y);
        int4 m1 = make_int4(base + v.x + v.y, v.z, base + v.x + v.y + v.z, v.w);
        *(int4*)(&g_meta[base4])     = m0;
        *(int4*)(&g_meta[base4 + 2]) = m1;
    } else {
        int b = base;
        if (base4 + 0 < N) { g_meta[base4 + 0] = make_int2(b, v.x); b += v.x; }
        if (base4 + 1 < N) { g_meta[base4 + 1] = make_int2(b, v.y); b += v.y; }
        if (base4 + 2 < N) { g_meta[base4 + 2] = make_int2(b, v.z); }
    }
}

// ---------------- main segmented loss + folded finalize -----------------------
struct SegS { unsigned db; int off; int cnt; };

__device__ __forceinline__ void seg_load(
    const float* __restrict__ pred, const float* __restrict__ gt,
    int s, int M, int lane, SegS& S)
{
    int2 mc = g_meta[s];
    S.off = mc.x; S.cnt = mc.y;

    float2 p01 = *(const float2*)(pred + (size_t)s * 6);
    int r = S.off + ((lane < S.cnt) ? lane : 0);
    r = (r < M - 1) ? r : (M - 1);
    float2 g01 = *(const float2*)(gt + (size_t)r * 6);

    float dx = p01.x - g01.x, dy = p01.y - g01.y;
    float d  = dx * dx + dy * dy;
    S.db = (lane < S.cnt) ? __float_as_uint(d) : 0x7f800000u;
}

__device__ __forceinline__ void seg_finish(
    const float* __restrict__ pred, const float* __restrict__ gt,
    int s, int lane, const SegS& S, float& a0, float& a1, float& a2, float& a3)
{
    unsigned mn   = __reduce_min_sync(FULL, S.db);     // min dist bits (nonneg fp)
    unsigned mask = __ballot_sync(FULL, S.db == mn);   // lowest lane = ref tie-break
    int win = __ffs(mask) - 1;
    if (S.cnt > 0 && lane == win) {
        float dmin = __uint_as_float(mn);
        const float* pr = pred + (size_t)s * 6;
        const float* gr = gt + (size_t)(S.off + win) * 6;
        float2 p23 = *(const float2*)(pr + 2);         // L1-hit (sector already pulled)
        float2 p45 = *(const float2*)(pr + 4);
        float2 g23 = *(const float2*)(gr + 2);
        float2 g45 = *(const float2*)(gr + 4);

        a0 += 1.0f - expf(dmin * (-1.0f / 0.045f));    // 2*sigma^2 = 0.045
        a1 += fabsf(p23.x - g23.x) + fabsf(p23.y - g23.y);
        float dd = p45.x - g45.x, ad = fabsf(dd);
        a2 += (ad < 1.0f) ? 0.5f * dd * dd : ad - 0.5f;
        float x = p45.y, t = g45.y;
        if (t > 0.0f)
            a3 += fmaxf(x, 0.0f) - x * t + log1pf(expf(-fabsf(x)));
    }
}

__global__ void __launch_bounds__(256) k_main(
    const float* __restrict__ pred,
    const float* __restrict__ gt,
    float* __restrict__ out,
    int N, int M)
{
    const int lane   = threadIdx.x & 31;
    const int wInBlk = threadIdx.x >> 5;
    const int warpId = (blockIdx.x * blockDim.x + threadIdx.x) >> 5;
    const int nWarps = (gridDim.x * blockDim.x) >> 5;

    float a0 = 0.f, a1 = 0.f, a2 = 0.f, a3 = 0.f;

    int s = warpId;
    for (; s + 3 * nWarps < N; s += 4 * nWarps) {
        SegS S0, S1, S2, S3;
        seg_load(pred, gt, s,              M, lane, S0);   // 4 independent gt loads in flight
        seg_load(pred, gt, s +     nWarps, M, lane, S1);
        seg_load(pred, gt, s + 2 * nWarps, M, lane, S2);
        seg_load(pred, gt, s + 3 * nWarps, M, lane, S3);
        seg_finish(pred, gt, s,              lane, S0, a0, a1, a2, a3);
        seg_finish(pred, gt, s +     nWarps, lane, S1, a0, a1, a2, a3);
        seg_finish(pred, gt, s + 2 * nWarps, lane, S2, a0, a1, a2, a3);
        seg_finish(pred, gt, s + 3 * nWarps, lane, S3, a0, a1, a2, a3);
    }
    for (; s < N; s += nWarps) {
        SegS S0;
        seg_load(pred, gt, s, M, lane, S0);
        seg_finish(pred, gt, s, lane, S0, a0, a1, a2, a3);
    }

    // warp reduce (all lanes hold partials)
    #pragma unroll
    for (int o = 16; o; o >>= 1) {
        a0 += __shfl_xor_sync(FULL, a0, o);
        a1 += __shfl_xor_sync(FULL, a1, o);
        a2 += __shfl_xor_sync(FULL, a2, o);
        a3 += __shfl_xor_sync(FULL, a3, o);
    }

    __shared__ float sh[8][4];
    if (lane == 0) {
        sh[wInBlk][0] = a0; sh[wInBlk][1] = a1;
        sh[wInBlk][2] = a2; sh[wInBlk][3] = a3;
    }
    __syncthreads();
    if (threadIdx.x == 0) {
        float b0 = 0.f, b1 = 0.f, b2 = 0.f, b3 = 0.f;
        int nw = blockDim.x >> 5;
        for (int w = 0; w < nw; w++) {
            b0 += sh[w][0]; b1 += sh[w][1]; b2 += sh[w][2]; b3 += sh[w][3];
        }
        atomicAdd(&g_acc[0], (double)b0);
        atomicAdd(&g_acc[1], (double)b1);
        atomicAdd(&g_acc[2], (double)b2);
        atomicAdd(&g_acc[3], (double)b3);
        __threadfence();
        int done = atomicAdd(&g_done, 1);
        if (done == (int)gridDim.x - 1) {
            g_done = 0;                               // reset for next replay
            #pragma unroll
            for (int i = 0; i < MAX_NB; i++) g_state[i] = 0;   // reset lookback state
            double inv = 1.0 / (double)N;
            double lp = ((volatile double*)g_acc)[0] * inv;
            double la = ((volatile double*)g_acc)[1] * inv;
            double lw = ((volatile double*)g_acc)[2] * inv;
            double ls = ((volatile double*)g_acc)[3] * inv;
            out[0] = (float)lp;
            out[1] = (float)la;
            out[2] = (float)lw;
            out[3] = (float)ls;
            out[4] = (float)(lp + la + lw + 0.5 * ls);
        }
    }
}

extern "C" void kernel_launch(void* const* d_in, const int* in_sizes, int n_in,
                              void* d_out, int out_size) {
    const float* pred   = (const float*)d_in[0];
    const float* gt     = (const float*)d_in[1];
    const int*   counts = (const int*)d_in[2];
    float* out = (float*)d_out;

    int N = in_sizes[2];
    if (N > MAXN) N = MAXN;              // scratch guard (contract: N == 262144)
    int M = in_sizes[1] / 6;             // total gt rows
    int NB = (N + TILE - 1) / TILE;      // <= 64 tiles (all resident: lookback safe)

    k_scan<<<NB, SCAN_BLK>>>(counts, N);
    k_main<<<2048, 256>>>(pred, gt, out, N, M);
}

// round 9
// speedup vs baseline: 1.3061x; 1.3061x over previous
#include <cuda_runtime.h>
#include <math.h>

// ---------------- scratch (no allocation allowed) ----------------
#define MAXN   262144
#define SCAN_BLK 1024          // threads per scan block
#define TILE   4096            // segments per scan tile (4 per thread)
#define MAX_NB 64
#define FLAG_AGG  0x10000000
#define FLAG_INCL 0x20000000
#define VMASK     0x0FFFFFFF
#define FULL      0xffffffffu
__device__ __align__(16) int2 g_meta[MAXN];  // (exclusive offset, count) per segment
__device__ __align__(16) int2 g_win[MAXN];   // (winner row, dist bits) per segment
__device__ int    g_state[MAX_NB];   // decoupled-lookback state (zero-init, reset at finalize)
__device__ double g_acc[4];          // lp, la, lw, ls sums
__device__ int    g_done = 0;        // completion counter for folded finalize

// ------ kernel 1: single-pass scan, warp-parallel lookback (<=64 blocks) ------
__global__ void __launch_bounds__(SCAN_BLK) k_scan(const int* __restrict__ counts, int N) {
    __shared__ int wsum[32];
    __shared__ int s_ex;
    int tid = threadIdx.x, lane = tid & 31, w = tid >> 5;
    int base4 = blockIdx.x * TILE + tid * 4;

    int4 v = make_int4(0, 0, 0, 0);
    if (base4 + 3 < N) v = *(const int4*)(counts + base4);
    else {
        if (base4 + 0 < N) v.x = counts[base4 + 0];
        if (base4 + 1 < N) v.y = counts[base4 + 1];
        if (base4 + 2 < N) v.z = counts[base4 + 2];
        if (base4 + 3 < N) v.w = counts[base4 + 3];
    }
    int s = v.x + v.y + v.z + v.w;

    // warp inclusive scan of per-thread sums
    int si = s;
    #pragma unroll
    for (int o = 1; o < 32; o <<= 1) {
        int t = __shfl_up_sync(FULL, si, o);
        if (lane >= o) si += t;
    }
    if (lane == 31) wsum[w] = si;
    __syncthreads();
    if (w == 0) {
        int ws = wsum[lane];
        int wi = ws;
        #pragma unroll
        for (int o = 1; o < 32; o <<= 1) {
            int t = __shfl_up_sync(FULL, wi, o);
            if (lane >= o) wi += t;
        }
        wsum[lane] = wi - ws;                        // exclusive warp offset
        int total = __shfl_sync(FULL, wi, 31);       // tile aggregate

        if (lane == 0) {                             // publish
            if (blockIdx.x == 0) atomicExch(&g_state[0], total | FLAG_INCL);
            else                 atomicExch(&g_state[blockIdx.x], total | FLAG_AGG);
        }
        int ex = 0;
        if (blockIdx.x > 0) {                        // warp-parallel lookback
            int p = (int)blockIdx.x - 1;
            while (true) {
                int idx = p - lane;
                int st = (idx >= 0) ? atomicAdd(&g_state[idx], 0) : FLAG_INCL;
                while (__any_sync(FULL, st == 0))
                    st = (idx >= 0) ? atomicAdd(&g_state[idx], 0) : FLAG_INCL;
                unsigned im = __ballot_sync(FULL, (st & FLAG_INCL) != 0);
                if (im) {
                    int k = __ffs(im) - 1;           // nearest inclusive predecessor
                    int contrib = (lane <= k) ? (st & VMASK) : 0;
                    ex += __reduce_add_sync(FULL, contrib);
                    break;
                } else {
                    ex += __reduce_add_sync(FULL, st & VMASK);
                    p -= 32;
                }
            }
            if (lane == 0) atomicExch(&g_state[blockIdx.x], (ex + total) | FLAG_INCL);
        } else if (lane == 0) {
            g_acc[0] = 0.0; g_acc[1] = 0.0; g_acc[2] = 0.0; g_acc[3] = 0.0;
        }
        if (lane == 0) s_ex = ex;
    }
    __syncthreads();

    int base = s_ex + wsum[w] + (si - s);            // global exclusive prefix
    if (base4 + 3 < N) {
        int4 m0 = make_int4(base,             v.x, base + v.x,            v.y);
        int4 m1 = make_int4(base + v.x + v.y, v.z, base + v.x + v.y + v.z, v.w);
        *(int4*)(&g_meta[base4])     = m0;
        *(int4*)(&g_meta[base4 + 2]) = m1;
    } else {
        int b = base;
        if (base4 + 0 < N) { g_meta[base4 + 0] = make_int2(b, v.x); b += v.x; }
        if (base4 + 1 < N) { g_meta[base4 + 1] = make_int2(b, v.y); b += v.y; }
        if (base4 + 2 < N) { g_meta[base4 + 2] = make_int2(b, v.z); }
    }
}

// ---------------- pass 1: warp-per-segment argmin only ------------------------
__device__ __forceinline__ void p1_load(
    const float* __restrict__ pred, const float* __restrict__ gt,
    int s, int M, int lane, unsigned& db, int& off, int& cnt)
{
    int2 mc = g_meta[s];
    off = mc.x; cnt = mc.y;
    float2 p01 = *(const float2*)(pred + (size_t)s * 6);
    int r = off + ((lane < cnt) ? lane : 0);
    r = min(r, M - 1); r = max(r, 0);
    float2 g01 = *(const float2*)(gt + (size_t)r * 6);
    float dx = p01.x - g01.x, dy = p01.y - g01.y;
    float d  = dx * dx + dy * dy;
    db = (lane < cnt) ? __float_as_uint(d) : 0x7f800000u;
}

__device__ __forceinline__ void p1_finish(int s, int lane, unsigned db, int off, int cnt)
{
    unsigned mn   = __reduce_min_sync(FULL, db);       // min dist bits (nonneg fp)
    unsigned mask = __ballot_sync(FULL, db == mn);     // lowest lane = ref tie-break
    if (lane == 0 && cnt > 0)
        g_win[s] = make_int2(off + __ffs(mask) - 1, (int)mn);
}

__global__ void __launch_bounds__(256) k_pass1(
    const float* __restrict__ pred,
    const float* __restrict__ gt,
    int N, int M)
{
    const int lane   = threadIdx.x & 31;
    const int warpId = (blockIdx.x * blockDim.x + threadIdx.x) >> 5;
    const int nWarps = (gridDim.x * blockDim.x) >> 5;

    int s = warpId;
    for (; s + nWarps < N; s += 2 * nWarps) {
        unsigned dA, dB; int oA, cA, oB, cB;
        p1_load(pred, gt, s,          M, lane, dA, oA, cA);
        p1_load(pred, gt, s + nWarps, M, lane, dB, oB, cB);
        p1_finish(s,          lane, dA, oA, cA);
        p1_finish(s + nWarps, lane, dB, oB, cB);
    }
    if (s < N) {
        unsigned dA; int oA, cA;
        p1_load(pred, gt, s, M, lane, dA, oA, cA);
        p1_finish(s, lane, dA, oA, cA);
    }
}

// ---------------- pass 2: thread-per-segment losses + finalize ----------------
__global__ void __launch_bounds__(256) k_pass2(
    const float* __restrict__ pred,
    const float* __restrict__ gt,
    float* __restrict__ out,
    int N)
{
    const int lane   = threadIdx.x & 31;
    const int wInBlk = threadIdx.x >> 5;
    int s = blockIdx.x * blockDim.x + threadIdx.x;

    float l0 = 0.f, l1 = 0.f, l2 = 0.f, l3 = 0.f;
    if (s < N) {
        int cnt = g_meta[s].y;                 // coalesced
        if (cnt > 0) {
            int2 wv = g_win[s];                // coalesced
            float dmin = __uint_as_float((unsigned)wv.y);
            l0 = 1.0f - __expf(dmin * (-1.0f / 0.045f));   // 2*sigma^2 = 0.045

            const float* pr = pred + (size_t)s * 6;
            const float* gr = gt + (size_t)wv.x * 6;
            float2 p23 = *(const float2*)(pr + 2);
            float2 p45 = *(const float2*)(pr + 4);
            float2 g23 = *(const float2*)(gr + 2);
            float2 g45 = *(const float2*)(gr + 4);

            l1 = fabsf(p23.x - g23.x) + fabsf(p23.y - g23.y);
            float dd = p45.x - g45.x, ad = fabsf(dd);
            l2 = (ad < 1.0f) ? 0.5f * dd * dd : ad - 0.5f;
            float x = p45.y, t = g45.y;
            if (t > 0.0f) {
                float z = __expf(-fabsf(x));
                l3 = fmaxf(x, 0.0f) - x * t + __logf(1.0f + z);
            }
        }
    }

    // warp reduce
    #pragma unroll
    for (int o = 16; o; o >>= 1) {
        l0 += __shfl_xor_sync(FULL, l0, o);
        l1 += __shfl_xor_sync(FULL, l1, o);
        l2 += __shfl_xor_sync(FULL, l2, o);
        l3 += __shfl_xor_sync(FULL, l3, o);
    }

    __shared__ float sh[8][4];
    if (lane == 0) {
        sh[wInBlk][0] = l0; sh[wInBlk][1] = l1;
        sh[wInBlk][2] = l2; sh[wInBlk][3] = l3;
    }
    __syncthreads();
    if (threadIdx.x == 0) {
        float b0 = 0.f, b1 = 0.f, b2 = 0.f, b3 = 0.f;
        int nw = blockDim.x >> 5;
        for (int w = 0; w < nw; w++) {
            b0 += sh[w][0]; b1 += sh[w][1]; b2 += sh[w][2]; b3 += sh[w][3];
        }
        atomicAdd(&g_acc[0], (double)b0);
        atomicAdd(&g_acc[1], (double)b1);
        atomicAdd(&g_acc[2], (double)b2);
        atomicAdd(&g_acc[3], (double)b3);
        __threadfence();
        int done = atomicAdd(&g_done, 1);
        if (done == (int)gridDim.x - 1) {
            g_done = 0;                               // reset for next replay
            #pragma unroll
            for (int i = 0; i < MAX_NB; i++) g_state[i] = 0;   // reset lookback state
            double inv = 1.0 / (double)N;
            double lp = ((volatile double*)g_acc)[0] * inv;
            double la = ((volatile double*)g_acc)[1] * inv;
            double lw = ((volatile double*)g_acc)[2] * inv;
            double ls = ((volatile double*)g_acc)[3] * inv;
            out[0] = (float)lp;
            out[1] = (float)la;
            out[2] = (float)lw;
            out[3] = (float)ls;
            out[4] = (float)(lp + la + lw + 0.5 * ls);
        }
    }
}

extern "C" void kernel_launch(void* const* d_in, const int* in_sizes, int n_in,
                              void* d_out, int out_size) {
    const float* pred   = (const float*)d_in[0];
    const float* gt     = (const float*)d_in[1];
    const int*   counts = (const int*)d_in[2];
    float* out = (float*)d_out;

    int N = in_sizes[2];
    if (N > MAXN) N = MAXN;              // scratch guard (contract: N == 262144)
    int M = in_sizes[1] / 6;             // total gt rows
    int NB = (N + TILE - 1) / TILE;      // <= 64 tiles (all resident: lookback safe)

    k_scan<<<NB, SCAN_BLK>>>(counts, N);
    k_pass1<<<2048, 256>>>(pred, gt, N, M);
    k_pass2<<<(N + 255) / 256, 256>>>(pred, gt, out, N);
}